// round 1
// baseline (speedup 1.0000x reference)
#include <cuda_runtime.h>
#include <cuda_bf16.h>
#include <math.h>

// Problem constants
#define BATCH 256
#define TT    200
#define DIN   128
#define HH    256
#define OUTD  118
#define G3    768   // 3*H

// ---------------- scratch (static device globals; no allocation) -------------
__device__ float g_gx[(size_t)BATCH * TT * G3];   // reused for both layers (157MB)
__device__ float g_hseq[(size_t)BATCH * TT * HH]; // layer hidden sequence (52MB)
__device__ float g_hA[BATCH * HH];
__device__ float g_hB[BATCH * HH];

// ---------------------------------------------------------------------------
// GEMM: C[M][768] = A[M][K] @ W[768][K]^T + bias[768]
// 128x128 tile, 256 threads, 8x8 microtile, K-tile = 8, register prefetch.
// Requires M%128==0, K%8==0, 768%128==0 (all hold here).
// ---------------------------------------------------------------------------
__global__ __launch_bounds__(256) void gemm_bias_kernel(
    const float* __restrict__ A, const float* __restrict__ W,
    const float* __restrict__ bias, float* __restrict__ C,
    int M, int K)
{
    __shared__ float sa[8][128];
    __shared__ float sb[8][128];

    const int nb = blockIdx.x * 128;
    const int mb = blockIdx.y * 128;
    const int tid = threadIdx.x;
    const int tx = tid & 15;        // n sub
    const int ty = tid >> 4;        // m sub

    const int lrow = tid >> 1;            // 0..127
    const int lseg = (tid & 1) * 4;       // 0 or 4

    const float* Aptr = A + (size_t)(mb + lrow) * K + lseg;
    const float* Wptr = W + (size_t)(nb + lrow) * K + lseg;

    float acc[8][8];
#pragma unroll
    for (int i = 0; i < 8; i++)
#pragma unroll
        for (int j = 0; j < 8; j++) acc[i][j] = 0.f;

    // preload tile 0
    float4 av = *(const float4*)(Aptr);
    float4 bv = *(const float4*)(Wptr);

    const int nkt = K >> 3;
    for (int kt = 0; kt < nkt; kt++) {
        __syncthreads();   // previous compute done
        sa[lseg + 0][lrow] = av.x; sa[lseg + 1][lrow] = av.y;
        sa[lseg + 2][lrow] = av.z; sa[lseg + 3][lrow] = av.w;
        sb[lseg + 0][lrow] = bv.x; sb[lseg + 1][lrow] = bv.y;
        sb[lseg + 2][lrow] = bv.z; sb[lseg + 3][lrow] = bv.w;
        __syncthreads();
        if (kt + 1 < nkt) {
            av = *(const float4*)(Aptr + (kt + 1) * 8);
            bv = *(const float4*)(Wptr + (kt + 1) * 8);
        }
#pragma unroll
        for (int k = 0; k < 8; k++) {
            float a[8], b[8];
            *(float4*)(a)     = *(const float4*)&sa[k][ty * 8];
            *(float4*)(a + 4) = *(const float4*)&sa[k][ty * 8 + 4];
            *(float4*)(b)     = *(const float4*)&sb[k][tx * 8];
            *(float4*)(b + 4) = *(const float4*)&sb[k][tx * 8 + 4];
#pragma unroll
            for (int i = 0; i < 8; i++)
#pragma unroll
                for (int j = 0; j < 8; j++)
                    acc[i][j] += a[i] * b[j];
        }
    }

    // epilogue: add bias, store
    float bb[8];
#pragma unroll
    for (int j = 0; j < 8; j++) bb[j] = bias[nb + tx * 8 + j];
#pragma unroll
    for (int i = 0; i < 8; i++) {
        const int row = mb + ty * 8 + i;
        float* cp = C + (size_t)row * G3 + nb + tx * 8;
        float4 v0, v1;
        v0.x = acc[i][0] + bb[0]; v0.y = acc[i][1] + bb[1];
        v0.z = acc[i][2] + bb[2]; v0.w = acc[i][3] + bb[3];
        v1.x = acc[i][4] + bb[4]; v1.y = acc[i][5] + bb[5];
        v1.z = acc[i][6] + bb[6]; v1.w = acc[i][7] + bb[7];
        *(float4*)(cp)     = v0;
        *(float4*)(cp + 4) = v1;
    }
}

// ---------------------------------------------------------------------------
// One GRU timestep.
// grid: (8 j-tiles, 16 m-tiles), 128 threads.
// Each CTA: batch tile [16] x h-col tile [32], computing all 3 gate slices
// (cols j, 256+j, 512+j) so h can be updated locally.
// gh = h_prev @ Whh^T (+bhh in epilogue); gates applied with precomputed gx.
// ---------------------------------------------------------------------------
__global__ __launch_bounds__(128) void gru_step_kernel(
    const float* __restrict__ hprev,   // [256][256]
    const float* __restrict__ Whh,     // [768][256]
    const float* __restrict__ bhh,     // [768]
    const float* __restrict__ gx,      // [B][T][768]
    float* __restrict__ hout,          // [256][256]
    float* __restrict__ hseq,          // [B][T][256]
    int t)
{
    __shared__ float sh[16][17];        // [k][m]
    __shared__ float sw[3][16][33];     // [g][k][j]

    const int jb = blockIdx.x * 32;
    const int mb = blockIdx.y * 16;
    const int tid = threadIdx.x;
    const int tj = (tid & 15) * 2;
    const int tm = (tid >> 4) * 2;

    // loader index precompute
    const int e = tid * 2;
    const int hm = e >> 4;              // 0..15
    const int hk = e & 15;              // even
    const float* hrow = hprev + (size_t)(mb + hm) * HH + hk;

    // w loader: 12 elements/thread
    int wg[12], wj[12], wk[12];
    const float* wptr[12];
#pragma unroll
    for (int i = 0; i < 12; i++) {
        const int ee = tid + i * 128;
        wg[i] = ee >> 9;                // /512
        const int r = ee & 511;
        wj[i] = r >> 4;
        wk[i] = r & 15;
        wptr[i] = Whh + (size_t)(wg[i] * HH + jb + wj[i]) * HH + wk[i];
    }

    float accr[2][2] = {{0.f,0.f},{0.f,0.f}};
    float accz[2][2] = {{0.f,0.f},{0.f,0.f}};
    float accn[2][2] = {{0.f,0.f},{0.f,0.f}};

    // preload tile 0
    float2 hv = *(const float2*)(hrow);
    float wv[12];
#pragma unroll
    for (int i = 0; i < 12; i++) wv[i] = wptr[i][0];

    for (int kt = 0; kt < 16; kt++) {
        __syncthreads();   // previous tile compute done
        sh[hk][hm] = hv.x;
        sh[hk + 1][hm] = hv.y;
#pragma unroll
        for (int i = 0; i < 12; i++) sw[wg[i]][wk[i]][wj[i]] = wv[i];
        __syncthreads();
        if (kt + 1 < 16) {
            const int k0 = (kt + 1) * 16;
            hv = *(const float2*)(hrow + k0);
#pragma unroll
            for (int i = 0; i < 12; i++) wv[i] = wptr[i][k0];
        }
#pragma unroll
        for (int k = 0; k < 16; k++) {
            const float h0 = sh[k][tm];
            const float h1 = sh[k][tm + 1];
            const float wr0 = sw[0][k][tj], wr1 = sw[0][k][tj + 1];
            const float wz0 = sw[1][k][tj], wz1 = sw[1][k][tj + 1];
            const float wn0 = sw[2][k][tj], wn1 = sw[2][k][tj + 1];
            accr[0][0] += h0 * wr0; accr[0][1] += h0 * wr1;
            accr[1][0] += h1 * wr0; accr[1][1] += h1 * wr1;
            accz[0][0] += h0 * wz0; accz[0][1] += h0 * wz1;
            accz[1][0] += h1 * wz0; accz[1][1] += h1 * wz1;
            accn[0][0] += h0 * wn0; accn[0][1] += h0 * wn1;
            accn[1][0] += h1 * wn0; accn[1][1] += h1 * wn1;
        }
    }

    // epilogue: gates + h update
#pragma unroll
    for (int mi = 0; mi < 2; mi++) {
#pragma unroll
        for (int ji = 0; ji < 2; ji++) {
            const int b = mb + tm + mi;
            const int j = jb + tj + ji;
            const float ghr = accr[mi][ji] + bhh[j];
            const float ghz = accz[mi][ji] + bhh[HH + j];
            const float ghn = accn[mi][ji] + bhh[2 * HH + j];
            const float* gxp = gx + ((size_t)b * TT + t) * G3;
            const float r = 1.f / (1.f + expf(-(gxp[j] + ghr)));
            const float z = 1.f / (1.f + expf(-(gxp[HH + j] + ghz)));
            const float n = tanhf(gxp[2 * HH + j] + r * ghn);
            const float ho = hprev[(size_t)b * HH + j];
            const float hn = (1.f - z) * n + z * ho;
            hout[(size_t)b * HH + j] = hn;
            hseq[((size_t)b * TT + t) * HH + j] = hn;
        }
    }
}

// ---------------------------------------------------------------------------
// Final FC: out[b][o] = hseq[b][T-1][:] . fcW[o][:] + fcb[o]
// ---------------------------------------------------------------------------
__global__ __launch_bounds__(128) void fc_kernel(
    const float* __restrict__ hseq, const float* __restrict__ W,
    const float* __restrict__ bias, float* __restrict__ out)
{
    __shared__ float hs[HH];
    const int b = blockIdx.x;
    const float* hrow = hseq + ((size_t)b * TT + (TT - 1)) * HH;
    for (int i = threadIdx.x; i < HH; i += 128) hs[i] = hrow[i];
    __syncthreads();
    const int o = threadIdx.x;
    if (o < OUTD) {
        float acc = bias[o];
        const float* wr = W + (size_t)o * HH;
#pragma unroll 8
        for (int k = 0; k < HH; k++) acc += hs[k] * wr[k];
        out[(size_t)b * OUTD + o] = acc;
    }
}

// ---------------------------------------------------------------------------
extern "C" void kernel_launch(void* const* d_in, const int* in_sizes, int n_in,
                              void* d_out, int out_size)
{
    const float* x    = (const float*)d_in[0];
    const float* Wih0 = (const float*)d_in[1];
    const float* Whh0 = (const float*)d_in[2];
    const float* bih0 = (const float*)d_in[3];
    const float* bhh0 = (const float*)d_in[4];
    const float* Wih1 = (const float*)d_in[5];
    const float* Whh1 = (const float*)d_in[6];
    const float* bih1 = (const float*)d_in[7];
    const float* bhh1 = (const float*)d_in[8];
    const float* fcW  = (const float*)d_in[9];
    const float* fcb  = (const float*)d_in[10];
    float* out = (float*)d_out;

    float *gx, *hseq, *hA, *hB;
    cudaGetSymbolAddress((void**)&gx, g_gx);
    cudaGetSymbolAddress((void**)&hseq, g_hseq);
    cudaGetSymbolAddress((void**)&hA, g_hA);
    cudaGetSymbolAddress((void**)&hB, g_hB);

    const dim3 gemmGrid(G3 / 128, (BATCH * TT) / 128);
    const dim3 stepGrid(HH / 32, BATCH / 16);

    // ---- layer 0 ----
    gemm_bias_kernel<<<gemmGrid, 256>>>(x, Wih0, bih0, gx, BATCH * TT, DIN);
    cudaMemsetAsync(hA, 0, BATCH * HH * sizeof(float));
    for (int t = 0; t < TT; t++) {
        const float* hp = (t & 1) ? hB : hA;
        float* ho = (t & 1) ? hA : hB;
        gru_step_kernel<<<stepGrid, 128>>>(hp, Whh0, bhh0, gx, ho, hseq, t);
    }

    // ---- layer 1 ----
    gemm_bias_kernel<<<gemmGrid, 256>>>(hseq, Wih1, bih1, gx, BATCH * TT, HH);
    cudaMemsetAsync(hA, 0, BATCH * HH * sizeof(float));
    for (int t = 0; t < TT; t++) {
        const float* hp = (t & 1) ? hB : hA;
        float* ho = (t & 1) ? hA : hB;
        gru_step_kernel<<<stepGrid, 128>>>(hp, Whh1, bhh1, gx, ho, hseq, t);
    }

    // ---- final FC ----
    fc_kernel<<<BATCH, 128>>>(hseq, fcW, fcb, out);
}

// round 2
// speedup vs baseline: 1.7519x; 1.7519x over previous
#include <cuda_runtime.h>
#include <cuda_bf16.h>
#include <math.h>

// Problem constants
#define BATCH 256
#define TT    200
#define DIN   128
#define HH    256
#define OUTD  118
#define G3    768   // 3*H

// ---------------- scratch (static device globals; no allocation) -------------
__device__ float g_gx[(size_t)BATCH * TT * G3];   // reused for both layers
__device__ float g_hseq[(size_t)BATCH * TT * HH]; // layer hidden sequence
__device__ float g_hA[BATCH * HH];
__device__ float g_hB[BATCH * HH];
__device__ int   g_flags[16];

// ---------------------------------------------------------------------------
// GEMM: C[M][768] = A[M][K] @ W[768][K]^T + bias[768]   (unchanged from R1)
// ---------------------------------------------------------------------------
__global__ __launch_bounds__(256) void gemm_bias_kernel(
    const float* __restrict__ A, const float* __restrict__ W,
    const float* __restrict__ bias, float* __restrict__ C,
    int M, int K)
{
    __shared__ float sa[8][128];
    __shared__ float sb[8][128];

    const int nb = blockIdx.x * 128;
    const int mb = blockIdx.y * 128;
    const int tid = threadIdx.x;
    const int tx = tid & 15;
    const int ty = tid >> 4;

    const int lrow = tid >> 1;
    const int lseg = (tid & 1) * 4;

    const float* Aptr = A + (size_t)(mb + lrow) * K + lseg;
    const float* Wptr = W + (size_t)(nb + lrow) * K + lseg;

    float acc[8][8];
#pragma unroll
    for (int i = 0; i < 8; i++)
#pragma unroll
        for (int j = 0; j < 8; j++) acc[i][j] = 0.f;

    float4 av = *(const float4*)(Aptr);
    float4 bv = *(const float4*)(Wptr);

    const int nkt = K >> 3;
    for (int kt = 0; kt < nkt; kt++) {
        __syncthreads();
        sa[lseg + 0][lrow] = av.x; sa[lseg + 1][lrow] = av.y;
        sa[lseg + 2][lrow] = av.z; sa[lseg + 3][lrow] = av.w;
        sb[lseg + 0][lrow] = bv.x; sb[lseg + 1][lrow] = bv.y;
        sb[lseg + 2][lrow] = bv.z; sb[lseg + 3][lrow] = bv.w;
        __syncthreads();
        if (kt + 1 < nkt) {
            av = *(const float4*)(Aptr + (kt + 1) * 8);
            bv = *(const float4*)(Wptr + (kt + 1) * 8);
        }
#pragma unroll
        for (int k = 0; k < 8; k++) {
            float a[8], b[8];
            *(float4*)(a)     = *(const float4*)&sa[k][ty * 8];
            *(float4*)(a + 4) = *(const float4*)&sa[k][ty * 8 + 4];
            *(float4*)(b)     = *(const float4*)&sb[k][tx * 8];
            *(float4*)(b + 4) = *(const float4*)&sb[k][tx * 8 + 4];
#pragma unroll
            for (int i = 0; i < 8; i++)
#pragma unroll
                for (int j = 0; j < 8; j++)
                    acc[i][j] += a[i] * b[j];
        }
    }

    float bb[8];
#pragma unroll
    for (int j = 0; j < 8; j++) bb[j] = bias[nb + tx * 8 + j];
#pragma unroll
    for (int i = 0; i < 8; i++) {
        const int row = mb + ty * 8 + i;
        float* cp = C + (size_t)row * G3 + nb + tx * 8;
        float4 v0, v1;
        v0.x = acc[i][0] + bb[0]; v0.y = acc[i][1] + bb[1];
        v0.z = acc[i][2] + bb[2]; v0.w = acc[i][3] + bb[3];
        v1.x = acc[i][4] + bb[4]; v1.y = acc[i][5] + bb[5];
        v1.z = acc[i][6] + bb[6]; v1.w = acc[i][7] + bb[7];
        *(float4*)(cp)     = v0;
        *(float4*)(cp + 4) = v1;
    }
}

// ---------------------------------------------------------------------------
// Persistent GRU layer kernel: all 200 timesteps in ONE launch.
// grid (8 j-tiles, 16 m-tiles) = 128 CTAs, 128 threads, 1 CTA/SM (120KB smem).
// Each CTA keeps its Whh tile [3 gates][K=256][32 cols] in smem for the whole
// layer. Per step: stage h-tile [256k][16m] from L2 (__ldcg), FFMA GEMM from
// smem, gate math, write h + hseq, per-group flag sync (8 CTAs share mt).
// ---------------------------------------------------------------------------
#define WPAD 34   // j-dim padding (even => aligned float2)
#define HPAD 18   // m-dim padding (even => aligned float2)
#define SMEM_FLOATS (3 * 256 * WPAD + 256 * HPAD)

__device__ __forceinline__ float sigm(float x) {
    return __fdividef(1.f, 1.f + __expf(-x));
}
__device__ __forceinline__ float tanh_fast(float x) {
    // tanh(x) = 1 - 2/(e^{2x}+1); __expf inf-safe at both ends
    return 1.f - 2.f * __fdividef(1.f, __expf(2.f * x) + 1.f);
}

__global__ __launch_bounds__(128) void gru_layer_kernel(
    float* __restrict__ hA, float* __restrict__ hB,
    const float* __restrict__ Whh, const float* __restrict__ bhh,
    const float* __restrict__ gx,   // [B][T][768]
    float* __restrict__ hseq,       // [B][T][256]
    int* __restrict__ flags)
{
    extern __shared__ float smem[];
    float* sW = smem;                    // [(g*256+k)*WPAD + j]
    float* sh = smem + 3 * 256 * WPAD;   // [k*HPAD + m]

    const int jt = blockIdx.x;           // 0..7
    const int mt = blockIdx.y;           // 0..15
    const int jb = jt * 32;
    const int mb = mt * 16;
    const int tid = threadIdx.x;
    const int tx = tid & 15;
    const int ty = tid >> 4;             // 0..7
    const int tj = tx * 2;
    const int tm = ty * 2;

    // ---- one-time: load Whh tile into smem ----
    // 96 rows (3 gates x 32 cols), each 256 floats; threads 0..95 take one row.
    if (tid < 96) {
        const int g = tid >> 5;          // 0..2
        const int j = tid & 31;          // 0..31
        const float* wrow = Whh + (size_t)(g * HH + jb + j) * HH;
        float* dst = sW + j;             // + (g*256+k)*WPAD
#pragma unroll 4
        for (int k = 0; k < 256; k += 4) {
            float4 v = *(const float4*)(wrow + k);
            dst[(g * 256 + k + 0) * WPAD] = v.x;
            dst[(g * 256 + k + 1) * WPAD] = v.y;
            dst[(g * 256 + k + 2) * WPAD] = v.z;
            dst[(g * 256 + k + 3) * WPAD] = v.w;
        }
    }

    // constant per-thread bias (2 j cols x 3 gates)
    float bbr0 = bhh[jb + tj],          bbr1 = bhh[jb + tj + 1];
    float bbz0 = bhh[HH + jb + tj],     bbz1 = bhh[HH + jb + tj + 1];
    float bbn0 = bhh[2 * HH + jb + tj], bbn1 = bhh[2 * HH + jb + tj + 1];

    // h-stage loader mapping: m = tid&15, kb = (tid>>4)*32
    const int sm_ = tid & 15;
    const int skb = (tid >> 4) * 32;

    // gx base pointers for the 2 batch rows this thread owns
    const int b0 = mb + tm;
    const int b1 = mb + tm + 1;
    const float* gx0 = gx + (size_t)b0 * TT * G3;
    const float* gx1 = gx + (size_t)b1 * TT * G3;

    __syncthreads();   // sW ready

    for (int t = 0; t < TT; t++) {
        const float* rb = (t & 1) ? hB : hA;
        float*       wb = (t & 1) ? hA : hB;

        // wait for previous step's 8 producers of this batch group
        if (t > 0) {
            if (tid == 0) {
                const int tgt = 8 * t;
                const volatile int* f = flags + mt;
                while (*f < tgt) { }
            }
            __syncthreads();
        }

        // prefetch gx for this step (independent of h)
        const float* p0 = gx0 + (size_t)t * G3;
        const float* p1 = gx1 + (size_t)t * G3;
        const float gr00 = __ldg(p0 + jb + tj),          gr01 = __ldg(p0 + jb + tj + 1);
        const float gz00 = __ldg(p0 + HH + jb + tj),     gz01 = __ldg(p0 + HH + jb + tj + 1);
        const float gn00 = __ldg(p0 + 2*HH + jb + tj),   gn01 = __ldg(p0 + 2*HH + jb + tj + 1);
        const float gr10 = __ldg(p1 + jb + tj),          gr11 = __ldg(p1 + jb + tj + 1);
        const float gz10 = __ldg(p1 + HH + jb + tj),     gz11 = __ldg(p1 + HH + jb + tj + 1);
        const float gn10 = __ldg(p1 + 2*HH + jb + tj),   gn11 = __ldg(p1 + 2*HH + jb + tj + 1);

        // stage h tile [k=256][m=16] (L2 reads; bypass L1 for coherence)
        {
            const float* src = rb + (size_t)(mb + sm_) * HH + skb;
#pragma unroll
            for (int i = 0; i < 32; i += 4) {
                float4 v;
                v.x = __ldcg(src + i);
                v.y = __ldcg(src + i + 1);
                v.z = __ldcg(src + i + 2);
                v.w = __ldcg(src + i + 3);
                sh[(skb + i + 0) * HPAD + sm_] = v.x;
                sh[(skb + i + 1) * HPAD + sm_] = v.y;
                sh[(skb + i + 2) * HPAD + sm_] = v.z;
                sh[(skb + i + 3) * HPAD + sm_] = v.w;
            }
        }
        __syncthreads();

        // ---- GEMM from smem: 12 accumulators (2m x 2j x 3 gates) ----
        float ar00 = 0.f, ar01 = 0.f, ar10 = 0.f, ar11 = 0.f;
        float az00 = 0.f, az01 = 0.f, az10 = 0.f, az11 = 0.f;
        float an00 = 0.f, an01 = 0.f, an10 = 0.f, an11 = 0.f;

        const float* shp = sh + tm;
        const float* wr_ = sW + tj;
        const float* wz_ = sW + 256 * WPAD + tj;
        const float* wn_ = sW + 512 * WPAD + tj;

#pragma unroll 8
        for (int k = 0; k < 256; k++) {
            const float2 hv = *(const float2*)(shp + k * HPAD);
            const float2 wr = *(const float2*)(wr_ + k * WPAD);
            const float2 wz = *(const float2*)(wz_ + k * WPAD);
            const float2 wn = *(const float2*)(wn_ + k * WPAD);
            ar00 += hv.x * wr.x; ar01 += hv.x * wr.y;
            ar10 += hv.y * wr.x; ar11 += hv.y * wr.y;
            az00 += hv.x * wz.x; az01 += hv.x * wz.y;
            az10 += hv.y * wz.x; az11 += hv.y * wz.y;
            an00 += hv.x * wn.x; an01 += hv.x * wn.y;
            an10 += hv.y * wn.x; an11 += hv.y * wn.y;
        }

        // ---- gates + h update (h_old read back from smem stage) ----
        const int j0 = jb + tj, j1 = jb + tj + 1;
        const float ho00 = sh[j0 * HPAD + tm],     ho01 = sh[j1 * HPAD + tm];
        const float ho10 = sh[j0 * HPAD + tm + 1], ho11 = sh[j1 * HPAD + tm + 1];

        const float r00 = sigm(gr00 + ar00 + bbr0);
        const float r01 = sigm(gr01 + ar01 + bbr1);
        const float r10 = sigm(gr10 + ar10 + bbr0);
        const float r11 = sigm(gr11 + ar11 + bbr1);
        const float z00 = sigm(gz00 + az00 + bbz0);
        const float z01 = sigm(gz01 + az01 + bbz1);
        const float z10 = sigm(gz10 + az10 + bbz0);
        const float z11 = sigm(gz11 + az11 + bbz1);
        const float n00 = tanh_fast(gn00 + r00 * (an00 + bbn0));
        const float n01 = tanh_fast(gn01 + r01 * (an01 + bbn1));
        const float n10 = tanh_fast(gn10 + r10 * (an10 + bbn0));
        const float n11 = tanh_fast(gn11 + r11 * (an11 + bbn1));

        const float h00 = (1.f - z00) * n00 + z00 * ho00;
        const float h01 = (1.f - z01) * n01 + z01 * ho01;
        const float h10 = (1.f - z10) * n10 + z10 * ho10;
        const float h11 = (1.f - z11) * n11 + z11 * ho11;

        __stcg(wb + (size_t)b0 * HH + j0, h00);
        __stcg(wb + (size_t)b0 * HH + j1, h01);
        __stcg(wb + (size_t)b1 * HH + j0, h10);
        __stcg(wb + (size_t)b1 * HH + j1, h11);

        float* hs0 = hseq + ((size_t)b0 * TT + t) * HH;
        float* hs1 = hseq + ((size_t)b1 * TT + t) * HH;
        hs0[j0] = h00; hs0[j1] = h01;
        hs1[j0] = h10; hs1[j1] = h11;

        __threadfence();
        __syncthreads();
        if (tid == 0) atomicAdd(flags + mt, 1);
    }
}

// ---------------------------------------------------------------------------
// Final FC
// ---------------------------------------------------------------------------
__global__ __launch_bounds__(128) void fc_kernel(
    const float* __restrict__ hseq, const float* __restrict__ W,
    const float* __restrict__ bias, float* __restrict__ out)
{
    __shared__ float hs[HH];
    const int b = blockIdx.x;
    const float* hrow = hseq + ((size_t)b * TT + (TT - 1)) * HH;
    for (int i = threadIdx.x; i < HH; i += 128) hs[i] = hrow[i];
    __syncthreads();
    const int o = threadIdx.x;
    if (o < OUTD) {
        float acc = bias[o];
        const float* wr = W + (size_t)o * HH;
#pragma unroll 8
        for (int k = 0; k < HH; k++) acc += hs[k] * wr[k];
        out[(size_t)b * OUTD + o] = acc;
    }
}

// ---------------------------------------------------------------------------
extern "C" void kernel_launch(void* const* d_in, const int* in_sizes, int n_in,
                              void* d_out, int out_size)
{
    const float* x    = (const float*)d_in[0];
    const float* Wih0 = (const float*)d_in[1];
    const float* Whh0 = (const float*)d_in[2];
    const float* bih0 = (const float*)d_in[3];
    const float* bhh0 = (const float*)d_in[4];
    const float* Wih1 = (const float*)d_in[5];
    const float* Whh1 = (const float*)d_in[6];
    const float* bih1 = (const float*)d_in[7];
    const float* bhh1 = (const float*)d_in[8];
    const float* fcW  = (const float*)d_in[9];
    const float* fcb  = (const float*)d_in[10];
    float* out = (float*)d_out;

    float *gx, *hseq, *hA, *hB;
    int* flags;
    cudaGetSymbolAddress((void**)&gx, g_gx);
    cudaGetSymbolAddress((void**)&hseq, g_hseq);
    cudaGetSymbolAddress((void**)&hA, g_hA);
    cudaGetSymbolAddress((void**)&hB, g_hB);
    cudaGetSymbolAddress((void**)&flags, g_flags);

    static bool attr_set = false;
    if (!attr_set) {
        cudaFuncSetAttribute(gru_layer_kernel,
                             cudaFuncAttributeMaxDynamicSharedMemorySize,
                             SMEM_FLOATS * (int)sizeof(float));
        attr_set = true;
    }

    const dim3 gemmGrid(G3 / 128, (BATCH * TT) / 128);
    const dim3 layerGrid(8, 16);
    const int smemB = SMEM_FLOATS * (int)sizeof(float);

    // ---- layer 0 ----
    gemm_bias_kernel<<<gemmGrid, 256>>>(x, Wih0, bih0, gx, BATCH * TT, DIN);
    cudaMemsetAsync(hA, 0, BATCH * HH * sizeof(float));
    cudaMemsetAsync(flags, 0, 16 * sizeof(int));
    gru_layer_kernel<<<layerGrid, 128, smemB>>>(hA, hB, Whh0, bhh0, gx, hseq, flags);

    // ---- layer 1 ----
    gemm_bias_kernel<<<gemmGrid, 256>>>(hseq, Wih1, bih1, gx, BATCH * TT, HH);
    cudaMemsetAsync(hA, 0, BATCH * HH * sizeof(float));
    cudaMemsetAsync(flags, 0, 16 * sizeof(int));
    gru_layer_kernel<<<layerGrid, 128, smemB>>>(hA, hB, Whh1, bhh1, gx, hseq, flags);

    // ---- final FC ----
    fc_kernel<<<BATCH, 128>>>(hseq, fcW, fcb, out);
}